// round 7
// baseline (speedup 1.0000x reference)
#include <cuda_runtime.h>

// Fused ISTFT, 16x16 register-FFT + shfl-transpose version.
// B=16, C=2, F=257, T=2048, n_fft=512, hop=128, center=True.
// Block = 16 frames of one (b,c) stream; thread (fr, col) does 16-pt inverse
// FFTs in registers; the 16x16 mid-transpose is done with shfl_xor (width 16)
// inside each half-warp (one half-warp owns one frame row). 2 block barriers.

#define NFFT     512
#define NH       257
#define HOP      128
#define TFRAMES  2048
#define NBC      32
#define OUT_PER_BC 262016            // (T-1)*hop
#define THREADS  256
#define FPB      16                  // frames per block
#define FADV     13                  // frame advance per chunk
#define CHUNK    1664                // FADV*HOP
#define NCHUNK   158                 // ceil(262016/1664)
#define FRSTRIDE 265                 // float2 stride per frame row (odd)

// SMEM layout (bytes)
#define OFF_DATA 0
#define OFF_T5   (FPB * FRSTRIDE * 8)            // 33920
#define OFF_WSHP (OFF_T5 + 256 * 8)              // 35968
#define OFF_WSQ  (OFF_WSHP + 256 * 8)            // 38016
#define OFF_EINV (OFF_WSQ + 512 * 4)             // 40064
#define SMEM_BYTES (OFF_EINV + 128 * 4)          // 40576

__device__ __forceinline__ float2 cmul(float2 a, float2 b) {
    return make_float2(a.x * b.x - a.y * b.y, a.x * b.y + a.y * b.x);
}

// Fully-unrolled 16-pt inverse DFT (e^{+i}), DIF, in place.
// On exit, position j holds X[bitrev4(j)].
__device__ __forceinline__ void fft16(float2* v)
{
    const float WR[8] = { 1.f,  0.9238795325f,  0.7071067812f,  0.3826834324f,
                          0.f, -0.3826834324f, -0.7071067812f, -0.9238795325f };
    const float WI[8] = { 0.f,  0.3826834324f,  0.7071067812f,  0.9238795325f,
                          1.f,  0.9238795325f,  0.7071067812f,  0.3826834324f };
    #pragma unroll
    for (int i = 0; i < 8; i++) {
        float2 a = v[i], b = v[i + 8];
        v[i] = make_float2(a.x + b.x, a.y + b.y);
        float dr = a.x - b.x, di = a.y - b.y;
        v[i + 8] = make_float2(dr * WR[i] - di * WI[i], dr * WI[i] + di * WR[i]);
    }
    #pragma unroll
    for (int bb = 0; bb < 16; bb += 8)
        #pragma unroll
        for (int i = 0; i < 4; i++) {
            float2 a = v[bb + i], b = v[bb + i + 4];
            v[bb + i] = make_float2(a.x + b.x, a.y + b.y);
            float dr = a.x - b.x, di = a.y - b.y;
            v[bb + i + 4] = make_float2(dr * WR[2 * i] - di * WI[2 * i],
                                        dr * WI[2 * i] + di * WR[2 * i]);
        }
    #pragma unroll
    for (int bb = 0; bb < 16; bb += 4) {
        float2 a = v[bb], b = v[bb + 2];
        v[bb]     = make_float2(a.x + b.x, a.y + b.y);
        v[bb + 2] = make_float2(a.x - b.x, a.y - b.y);
        a = v[bb + 1]; b = v[bb + 3];
        v[bb + 1] = make_float2(a.x + b.x, a.y + b.y);
        v[bb + 3] = make_float2(-(a.y - b.y), a.x - b.x);   // * i
    }
    #pragma unroll
    for (int bb = 0; bb < 16; bb += 2) {
        float2 a = v[bb], b = v[bb + 1];
        v[bb]     = make_float2(a.x + b.x, a.y + b.y);
        v[bb + 1] = make_float2(a.x - b.x, a.y - b.y);
    }
}

__global__ __launch_bounds__(THREADS, 4)
void istft_fused16s_kernel(const float2* __restrict__ X,
                           const float* __restrict__ win,
                           float* __restrict__ out)
{
    extern __shared__ char smem[];
    float2* D    = (float2*)(smem + OFF_DATA);
    float*  Frf  = (float*)(smem + OFF_DATA);
    float2* T5   = (float2*)(smem + OFF_T5);
    float2* wshp = (float2*)(smem + OFF_WSHP);
    float*  wsq  = (float*)(smem + OFF_WSQ);
    float*  einv = (float*)(smem + OFF_EINV);

    const int tid   = threadIdx.x;
    const int b     = blockIdx.x;
    const int bc    = blockIdx.y;
    const int tbase = FADV * b - 1;
    const int o0    = 256 + CHUNK * b;

    const int REV4[16] = {0,8,4,12,2,10,6,14,1,9,5,13,3,11,7,15};

    // ---- tables ----
    for (int k = tid; k < 256; k += THREADS) {
        float s, c; sincospif(k * (1.0f / 256.0f), &s, &c);
        T5[k] = make_float2(c, s);
    }
    for (int m = tid; m < 256; m += THREADS)
        wshp[m] = make_float2(win[2 * m] * (1.0f / 256.0f),
                              win[2 * m + 1] * (1.0f / 256.0f));
    for (int n = tid; n < NFFT; n += THREADS) {
        const float w = win[n];
        wsq[n] = w * w;
    }
    if (tid < 128) {
        const float w0 = win[tid], w1 = win[tid + 128],
                    w2 = win[tid + 256], w3 = win[tid + 384];
        einv[tid] = 1.0f / (w0 * w0 + w1 * w1 + w2 * w2 + w3 * w3);
    }

    // ---- stage input: 16 frames x 257 bins ----
    for (int idx = tid; idx < FPB * NH; idx += THREADS) {
        const int k  = idx >> 4;
        const int fr = idx & 15;
        int t = tbase + fr;
        t = t < 0 ? 0 : (t > TFRAMES - 1 ? TFRAMES - 1 : t);
        D[fr * FRSTRIDE + k] = X[(size_t)(bc * NH + k) * TFRAMES + t];
    }
    __syncthreads();                              // barrier 1 (tables + staging)

    const int fr  = tid >> 4;
    const int col = tid & 15;                     // n1 for phase A, k2 for phase B
    float2* row = D + fr * FRSTRIDE;
    float2 v[16];

    // ---- phase A: pack onesided->complex on the fly, fft16 over n2 ----
    #pragma unroll
    for (int n2 = 0; n2 < 16; n2++) {
        const int n = col + 16 * n2;
        float2 a = row[n];
        float2 t = row[256 - n];
        float br = t.x, bi = -t.y;
        if (n == 0) { a.y = 0.0f; bi = 0.0f; }    // C2R ignores DC/Nyquist imag
        const float zer = 0.5f * (a.x + br);
        const float zei = 0.5f * (a.y + bi);
        const float dr  = a.x - br;
        const float di  = a.y - bi;
        const float u   = -0.5f * di;
        const float w_  =  0.5f * dr;
        const float2 w  = T5[n];
        v[n2] = make_float2(zer + w.x * u - w.y * w_,
                            zei + w.x * w_ + w.y * u);
    }
    fft16(v);

    // ---- twiddle W256^{n1*k2} + un-bitrev into t[] (natural k2 order) ----
    float2 t[16];
    {
        const float2 w = T5[2 * col];             // cis(2*pi*n1/256)
        float2 tw = make_float2(1.0f, 0.0f);
        #pragma unroll
        for (int k2 = 0; k2 < 16; k2++) {
            t[k2] = cmul(v[REV4[k2]], tw);
            tw = cmul(tw, w);
        }
    }

    // ---- register transpose via shfl_xor within 16-lane groups ----
    // (thread n1, reg k2) -> (thread k2, reg n1); for each bit m, elements with
    // (lane&m) != (reg&m) hop to lane^m / reg^m.
    #pragma unroll
    for (int m = 1; m < 16; m <<= 1) {
        const bool sel = (col & m) != 0;
        #pragma unroll
        for (int j0 = 0; j0 < 16; j0++) {
            if (j0 & m) continue;                 // pairs (j0, j0|m)
            const int j1 = j0 | m;
            float2 tmp = sel ? t[j0] : t[j1];
            tmp.x = __shfl_xor_sync(0xFFFFFFFFu, tmp.x, m, 16);
            tmp.y = __shfl_xor_sync(0xFFFFFFFFu, tmp.y, m, 16);
            if (sel) t[j0] = tmp; else t[j1] = tmp;
        }
    }
    __syncwarp();                                 // row fr reads done (half-warp local)

    // ---- phase B: fft16 over n1; windowed frame write (in-place, warp-local) ----
    fft16(t);
    #pragma unroll
    for (int k1 = 0; k1 < 16; k1++) {
        const int m = col + 16 * k1;              // here col = k2
        const float2 z  = t[REV4[k1]];
        const float2 wp = wshp[m];
        row[m] = make_float2(z.x * wp.x, z.y * wp.y);
    }
    __syncthreads();                              // barrier 2 (frames ready)

    // ---- overlap-add + envelope normalize ----
    const int nsamp = min(CHUNK, 262272 - o0);
    const size_t obase = (size_t)bc * OUT_PER_BC;
    for (int j = tid; j < nsamp; j += THREADS) {
        const int m = o0 + j;
        if (m >= 384 && m < 262144) {
            // interior: exactly 4 contributing frames, fixed stride in smem
            const int t0   = (m - 384) >> 7;
            const int base = (t0 - tbase) * (2 * FRSTRIDE) + (m - (t0 << 7));
            const float acc = Frf[base] + Frf[base + 402] +
                              Frf[base + 804] + Frf[base + 1206];
            out[obase + (m - 256)] = acc * einv[m & 127];
        } else {
            int thi = m >> 7;          if (thi > TFRAMES - 1) thi = TFRAMES - 1;
            int tlo = (m - 384) >> 7;  if (tlo < 0) tlo = 0;
            float acc = 0.0f, e = 0.0f;
            for (int t_ = tlo; t_ <= thi; t_++) {
                const int n = m - (t_ << 7);
                acc += Frf[(t_ - tbase) * (2 * FRSTRIDE) + n];
                e   += wsq[n];
            }
            out[obase + (m - 256)] = acc / e;
        }
    }
}

extern "C" void kernel_launch(void* const* d_in, const int* in_sizes, int n_in,
                              void* d_out, int out_size)
{
    const float2* X   = (const float2*)d_in[0];   // (16,2,257,2048,2) f32
    const float*  win = (const float*)d_in[1];    // (512,) f32
    float* out = (float*)d_out;                   // (16,2,262016) f32

    dim3 grid(NCHUNK, NBC);
    istft_fused16s_kernel<<<grid, THREADS, SMEM_BYTES>>>(X, win, out);
}

// round 11
// speedup vs baseline: 1.0326x; 1.0326x over previous
#include <cuda_runtime.h>

// Fused ISTFT, 16x16 register-FFT, chain-free twiddles + DIT phase B + vec4 OLA.
// B=16, C=2, F=257, T=2048, n_fft=512, hop=128, center=True.

#define NFFT     512
#define NH       257
#define HOP      128
#define TFRAMES  2048
#define NBC      32
#define OUT_PER_BC 262016            // (T-1)*hop
#define THREADS  256
#define FPB      16                  // frames per block
#define FADV     13                  // frame advance per chunk
#define CHUNK    1664                // FADV*HOP
#define NCHUNK   158                 // ceil(262016/1664)
#define FRSTRIDE 264                 // float2 stride per frame row (528 floats, %4==0)

// SMEM layout (bytes)
#define OFF_DATA 0
#define OFF_T5   (FPB * FRSTRIDE * 8)            // 33792
#define OFF_TTW  (OFF_T5 + 256 * 8)              // 35840
#define OFF_WSHP (OFF_TTW + 16 * 17 * 8)         // 38016
#define OFF_WSQ  (OFF_WSHP + 256 * 8)            // 40064
#define OFF_EINV (OFF_WSQ + 512 * 4)             // 42112
#define SMEM_BYTES (OFF_EINV + 128 * 4)          // 42624

__device__ __forceinline__ float2 cmul(float2 a, float2 b) {
    return make_float2(a.x * b.x - a.y * b.y, a.x * b.y + a.y * b.x);
}

// 16-pt inverse DFT (e^{+i}), DIF, natural input -> bit-reversed output.
__device__ __forceinline__ void fft16_dif(float2* v)
{
    const float WR[8] = { 1.f,  0.9238795325f,  0.7071067812f,  0.3826834324f,
                          0.f, -0.3826834324f, -0.7071067812f, -0.9238795325f };
    const float WI[8] = { 0.f,  0.3826834324f,  0.7071067812f,  0.9238795325f,
                          1.f,  0.9238795325f,  0.7071067812f,  0.3826834324f };
    #pragma unroll
    for (int i = 0; i < 8; i++) {
        float2 a = v[i], b = v[i + 8];
        v[i] = make_float2(a.x + b.x, a.y + b.y);
        float dr = a.x - b.x, di = a.y - b.y;
        v[i + 8] = make_float2(dr * WR[i] - di * WI[i], dr * WI[i] + di * WR[i]);
    }
    #pragma unroll
    for (int bb = 0; bb < 16; bb += 8)
        #pragma unroll
        for (int i = 0; i < 4; i++) {
            float2 a = v[bb + i], b = v[bb + i + 4];
            v[bb + i] = make_float2(a.x + b.x, a.y + b.y);
            float dr = a.x - b.x, di = a.y - b.y;
            v[bb + i + 4] = make_float2(dr * WR[2 * i] - di * WI[2 * i],
                                        dr * WI[2 * i] + di * WR[2 * i]);
        }
    #pragma unroll
    for (int bb = 0; bb < 16; bb += 4) {
        float2 a = v[bb], b = v[bb + 2];
        v[bb]     = make_float2(a.x + b.x, a.y + b.y);
        v[bb + 2] = make_float2(a.x - b.x, a.y - b.y);
        a = v[bb + 1]; b = v[bb + 3];
        v[bb + 1] = make_float2(a.x + b.x, a.y + b.y);
        v[bb + 3] = make_float2(-(a.y - b.y), a.x - b.x);   // * i
    }
    #pragma unroll
    for (int bb = 0; bb < 16; bb += 2) {
        float2 a = v[bb], b = v[bb + 1];
        v[bb]     = make_float2(a.x + b.x, a.y + b.y);
        v[bb + 1] = make_float2(a.x - b.x, a.y - b.y);
    }
}

// 16-pt inverse DFT (e^{+i}), DIT, bit-reversed input -> natural output.
__device__ __forceinline__ void fft16_dit(float2* v)
{
    const float WR[8] = { 1.f,  0.9238795325f,  0.7071067812f,  0.3826834324f,
                          0.f, -0.3826834324f, -0.7071067812f, -0.9238795325f };
    const float WI[8] = { 0.f,  0.3826834324f,  0.7071067812f,  0.9238795325f,
                          1.f,  0.9238795325f,  0.7071067812f,  0.3826834324f };
    #pragma unroll
    for (int i = 0; i < 16; i += 2) {             // len=2
        float2 a = v[i], b = v[i + 1];
        v[i]     = make_float2(a.x + b.x, a.y + b.y);
        v[i + 1] = make_float2(a.x - b.x, a.y - b.y);
    }
    #pragma unroll
    for (int i = 0; i < 16; i += 4) {             // len=4, w = {1, i}
        float2 a = v[i], b = v[i + 2];
        v[i]     = make_float2(a.x + b.x, a.y + b.y);
        v[i + 2] = make_float2(a.x - b.x, a.y - b.y);
        a = v[i + 1]; b = v[i + 3];
        const float sr = -b.y, si = b.x;          // i*b
        v[i + 1] = make_float2(a.x + sr, a.y + si);
        v[i + 3] = make_float2(a.x - sr, a.y - si);
    }
    #pragma unroll
    for (int i = 0; i < 16; i += 8)               // len=8, w = W8^jj
        #pragma unroll
        for (int jj = 0; jj < 4; jj++) {
            float2 a = v[i + jj], b = v[i + jj + 4];
            const float sr = b.x * WR[2 * jj] - b.y * WI[2 * jj];
            const float si = b.x * WI[2 * jj] + b.y * WR[2 * jj];
            v[i + jj]     = make_float2(a.x + sr, a.y + si);
            v[i + jj + 4] = make_float2(a.x - sr, a.y - si);
        }
    #pragma unroll
    for (int jj = 0; jj < 8; jj++) {              // len=16, w = W16^jj
        float2 a = v[jj], b = v[jj + 8];
        const float sr = b.x * WR[jj] - b.y * WI[jj];
        const float si = b.x * WI[jj] + b.y * WR[jj];
        v[jj]     = make_float2(a.x + sr, a.y + si);
        v[jj + 8] = make_float2(a.x - sr, a.y - si);
    }
}

__global__ __launch_bounds__(THREADS, 4)
void istft_fused16t_kernel(const float2* __restrict__ X,
                           const float* __restrict__ win,
                           float* __restrict__ out)
{
    extern __shared__ char smem[];
    float2* D    = (float2*)(smem + OFF_DATA);
    float*  Frf  = (float*)(smem + OFF_DATA);
    float2* T5   = (float2*)(smem + OFF_T5);     // cis(2*pi*k/512)
    float2* Ttw  = (float2*)(smem + OFF_TTW);    // cis(2*pi*n1*k2/256), stride 17
    float2* wshp = (float2*)(smem + OFF_WSHP);
    float*  wsq  = (float*)(smem + OFF_WSQ);
    float*  einv = (float*)(smem + OFF_EINV);

    const int tid   = threadIdx.x;
    const int b     = blockIdx.x;
    const int bc    = blockIdx.y;
    const int tbase = FADV * b - 1;
    const int o0    = 256 + CHUNK * b;

    const int REV4[16] = {0,8,4,12,2,10,6,14,1,9,5,13,3,11,7,15};

    // ---- tables ----
    for (int k = tid; k < 256; k += THREADS) {
        float s, c; sincospif(k * (1.0f / 256.0f), &s, &c);
        T5[k] = make_float2(c, s);
    }
    {
        const int n1 = tid >> 4, k2 = tid & 15;
        float s, c; sincospif((n1 * k2) * (1.0f / 128.0f), &s, &c);
        Ttw[n1 * 17 + k2] = make_float2(c, s);
    }
    for (int m = tid; m < 256; m += THREADS)
        wshp[m] = make_float2(win[2 * m] * (1.0f / 256.0f),
                              win[2 * m + 1] * (1.0f / 256.0f));
    for (int n = tid; n < NFFT; n += THREADS) {
        const float w = win[n];
        wsq[n] = w * w;
    }
    if (tid < 128) {
        const float w0 = win[tid], w1 = win[tid + 128],
                    w2 = win[tid + 256], w3 = win[tid + 384];
        einv[tid] = 1.0f / (w0 * w0 + w1 * w1 + w2 * w2 + w3 * w3);
    }

    // ---- stage input: 16 frames x 257 bins ----
    for (int idx = tid; idx < FPB * NH; idx += THREADS) {
        const int k  = idx >> 4;
        const int fr = idx & 15;
        int t = tbase + fr;
        t = t < 0 ? 0 : (t > TFRAMES - 1 ? TFRAMES - 1 : t);
        D[fr * FRSTRIDE + k] = X[(size_t)(bc * NH + k) * TFRAMES + t];
    }
    __syncthreads();                              // barrier 1

    const int fr  = tid >> 4;
    const int col = tid & 15;                     // n1 for phase A, k2 for phase B
    float2* row = D + fr * FRSTRIDE;
    float2 v[16];

    // ---- phase A: pack onesided->complex, fft16 over n2 (DIF, bitrev out) ----
    #pragma unroll
    for (int n2 = 0; n2 < 16; n2++) {
        const int n = col + 16 * n2;
        float2 a = row[n];
        float2 t = row[256 - n];
        float br = t.x, bi = -t.y;
        if (n == 0) { a.y = 0.0f; bi = 0.0f; }    // C2R ignores DC/Nyquist imag
        const float zer = 0.5f * (a.x + br);
        const float zei = 0.5f * (a.y + bi);
        const float dr  = a.x - br;
        const float di  = a.y - bi;
        const float u   = -0.5f * di;
        const float w_  =  0.5f * dr;
        const float2 w  = T5[n];
        v[n2] = make_float2(zer + w.x * u - w.y * w_,
                            zei + w.x * w_ + w.y * u);
    }
    fft16_dif(v);                                 // v[j] = G[n1][REV4[j]]

    // ---- in-place twiddle W256^{n1*k2} via padded table (no chain, no copy) ----
    #pragma unroll
    for (int j = 0; j < 16; j++)
        v[j] = cmul(v[j], Ttw[col * 17 + REV4[j]]);

    // ---- shfl transpose with REV4-mapped reg bits ----
    // lane-space bit m pairs reg slots differing in bit REV4(m).
    {
        const int MM[4] = {1, 2, 4, 8};
        const int MR[4] = {8, 4, 2, 1};
        #pragma unroll
        for (int r = 0; r < 4; r++) {
            const int m = MM[r], mr = MR[r];
            const bool sel = (col & m) != 0;
            #pragma unroll
            for (int j0 = 0; j0 < 16; j0++) {
                if (j0 & mr) continue;
                const int j1 = j0 | mr;
                float2 tmp = sel ? v[j0] : v[j1];
                tmp.x = __shfl_xor_sync(0xFFFFFFFFu, tmp.x, m, 16);
                tmp.y = __shfl_xor_sync(0xFFFFFFFFu, tmp.y, m, 16);
                if (sel) v[j0] = tmp; else v[j1] = tmp;
            }
        }
    }
    // now: lane k2, reg j holds H[REV4[j]][k2] -> bitrev input for DIT

    // ---- phase B: fft16 over n1 (DIT, natural out); windowed frame write ----
    fft16_dit(v);
    #pragma unroll
    for (int k1 = 0; k1 < 16; k1++) {
        const int m = col + 16 * k1;              // col = k2 here
        const float2 z  = v[k1];
        const float2 wp = wshp[m];
        row[m] = make_float2(z.x * wp.x, z.y * wp.y);
    }
    __syncthreads();                              // barrier 2

    // ---- overlap-add + envelope normalize (vectorized x4) ----
    const int ngroups = min(CHUNK, 262272 - o0) >> 2;   // nsamp divisible by 4
    const size_t obase = (size_t)bc * OUT_PER_BC;
    for (int g = tid; g < ngroups; g += THREADS) {
        const int m0 = o0 + 4 * g;
        if (m0 >= 384 && m0 + 3 < 262144) {
            // interior: one t0 for the whole 4-group (group is 4-aligned)
            const int t0   = (m0 - 384) >> 7;
            const int n0   = m0 - (t0 << 7);                  // 384..508, %4==0
            const int base = (t0 - tbase) * (2 * FRSTRIDE) + n0;  // %4==0
            const float4 a = *(const float4*)(Frf + base);
            const float4 bb = *(const float4*)(Frf + base + 400);
            const float4 c = *(const float4*)(Frf + base + 800);
            const float4 d = *(const float4*)(Frf + base + 1200);
            const float4 e = *(const float4*)(einv + (n0 & 127));
            float4 r;
            r.x = (a.x + bb.x + c.x + d.x) * e.x;
            r.y = (a.y + bb.y + c.y + d.y) * e.y;
            r.z = (a.z + bb.z + c.z + d.z) * e.z;
            r.w = (a.w + bb.w + c.w + d.w) * e.w;
            *(float4*)(out + obase + (m0 - 256)) = r;
        } else {
            #pragma unroll
            for (int q = 0; q < 4; q++) {
                const int m = m0 + q;
                int thi = m >> 7;          if (thi > TFRAMES - 1) thi = TFRAMES - 1;
                int tlo = (m - 384) >> 7;  if (tlo < 0) tlo = 0;
                float acc = 0.0f, e = 0.0f;
                for (int t_ = tlo; t_ <= thi; t_++) {
                    const int n = m - (t_ << 7);
                    acc += Frf[(t_ - tbase) * (2 * FRSTRIDE) + n];
                    e   += wsq[n];
                }
                out[obase + (m - 256)] = acc / e;
            }
        }
    }
}

extern "C" void kernel_launch(void* const* d_in, const int* in_sizes, int n_in,
                              void* d_out, int out_size)
{
    const float2* X   = (const float2*)d_in[0];   // (16,2,257,2048,2) f32
    const float*  win = (const float*)d_in[1];    // (512,) f32
    float* out = (float*)d_out;                   // (16,2,262016) f32

    dim3 grid(NCHUNK, NBC);
    istft_fused16t_kernel<<<grid, THREADS, SMEM_BYTES>>>(X, win, out);
}

// round 14
// speedup vs baseline: 1.0507x; 1.0175x over previous
#include <cuda_runtime.h>

// Fused ISTFT, 16x16 register-FFT; tables precomputed ONCE by an init kernel
// into __device__ globals (8.8 KB), copied to SMEM per block (L2 broadcast).
// B=16, C=2, F=257, T=2048, n_fft=512, hop=128, center=True.

#define NFFT     512
#define NH       257
#define HOP      128
#define TFRAMES  2048
#define NBC      32
#define OUT_PER_BC 262016            // (T-1)*hop
#define THREADS  256
#define FPB      16                  // frames per block
#define FADV     13                  // frame advance per chunk
#define CHUNK    1664                // FADV*HOP
#define NCHUNK   158                 // ceil(262016/1664)
#define FRSTRIDE 264                 // float2 stride per frame row (528 floats, %4==0)

// SMEM layout (bytes) — table region is one contiguous copy of struct Tables
#define OFF_DATA 0
#define OFF_T5   (FPB * FRSTRIDE * 8)            // 33792
#define OFF_TTW  (OFF_T5 + 256 * 8)              // 35840
#define OFF_WSHP (OFF_TTW + 272 * 8)             // 38016
#define OFF_WSQ  (OFF_WSHP + 256 * 8)            // 40064
#define OFF_EINV (OFF_WSQ + 512 * 4)             // 42112
#define SMEM_BYTES (OFF_EINV + 128 * 4)          // 42624
#define TAB_BYTES  (SMEM_BYTES - OFF_T5)         // 8832
#define TAB_VEC4   (TAB_BYTES / 16)              // 552

struct __align__(16) Tables {
    float2 T5[256];      // cis(2*pi*k/512)
    float2 Ttw[272];     // cis(2*pi*n1*k2/256), stride 17 (holes unused)
    float2 wshp[256];    // (win[2m], win[2m+1]) / 256
    float  wsq[512];     // win^2
    float  einv[128];    // 1/env interior
};
static __device__ Tables g_tab;

__global__ void istft_init_tables(const float* __restrict__ win)
{
    const int tid = threadIdx.x;                  // 256 threads, 1 block
    {
        float s, c; sincospif(tid * (1.0f / 256.0f), &s, &c);   // 2*pi*tid/512
        g_tab.T5[tid] = make_float2(c, s);
    }
    {
        const int n1 = tid >> 4, k2 = tid & 15;
        float s, c; sincospif((n1 * k2) * (1.0f / 128.0f), &s, &c);
        g_tab.Ttw[n1 * 17 + k2] = make_float2(c, s);
    }
    g_tab.wshp[tid] = make_float2(win[2 * tid] * (1.0f / 256.0f),
                                  win[2 * tid + 1] * (1.0f / 256.0f));
    {
        const float w0 = win[tid], w1 = win[tid + 256];
        g_tab.wsq[tid]       = w0 * w0;
        g_tab.wsq[tid + 256] = w1 * w1;
    }
    if (tid < 128) {
        const float w0 = win[tid], w1 = win[tid + 128],
                    w2 = win[tid + 256], w3 = win[tid + 384];
        g_tab.einv[tid] = 1.0f / (w0 * w0 + w1 * w1 + w2 * w2 + w3 * w3);
    }
    // fill Ttw holes (indices 16 mod 17) deterministically
    if (tid < 16) g_tab.Ttw[tid * 17 + 16] = make_float2(0.0f, 0.0f);
}

__device__ __forceinline__ float2 cmul(float2 a, float2 b) {
    return make_float2(a.x * b.x - a.y * b.y, a.x * b.y + a.y * b.x);
}

// 16-pt inverse DFT (e^{+i}), DIF, natural input -> bit-reversed output.
__device__ __forceinline__ void fft16_dif(float2* v)
{
    const float WR[8] = { 1.f,  0.9238795325f,  0.7071067812f,  0.3826834324f,
                          0.f, -0.3826834324f, -0.7071067812f, -0.9238795325f };
    const float WI[8] = { 0.f,  0.3826834324f,  0.7071067812f,  0.9238795325f,
                          1.f,  0.9238795325f,  0.7071067812f,  0.3826834324f };
    #pragma unroll
    for (int i = 0; i < 8; i++) {
        float2 a = v[i], b = v[i + 8];
        v[i] = make_float2(a.x + b.x, a.y + b.y);
        float dr = a.x - b.x, di = a.y - b.y;
        v[i + 8] = make_float2(dr * WR[i] - di * WI[i], dr * WI[i] + di * WR[i]);
    }
    #pragma unroll
    for (int bb = 0; bb < 16; bb += 8)
        #pragma unroll
        for (int i = 0; i < 4; i++) {
            float2 a = v[bb + i], b = v[bb + i + 4];
            v[bb + i] = make_float2(a.x + b.x, a.y + b.y);
            float dr = a.x - b.x, di = a.y - b.y;
            v[bb + i + 4] = make_float2(dr * WR[2 * i] - di * WI[2 * i],
                                        dr * WI[2 * i] + di * WR[2 * i]);
        }
    #pragma unroll
    for (int bb = 0; bb < 16; bb += 4) {
        float2 a = v[bb], b = v[bb + 2];
        v[bb]     = make_float2(a.x + b.x, a.y + b.y);
        v[bb + 2] = make_float2(a.x - b.x, a.y - b.y);
        a = v[bb + 1]; b = v[bb + 3];
        v[bb + 1] = make_float2(a.x + b.x, a.y + b.y);
        v[bb + 3] = make_float2(-(a.y - b.y), a.x - b.x);   // * i
    }
    #pragma unroll
    for (int bb = 0; bb < 16; bb += 2) {
        float2 a = v[bb], b = v[bb + 1];
        v[bb]     = make_float2(a.x + b.x, a.y + b.y);
        v[bb + 1] = make_float2(a.x - b.x, a.y - b.y);
    }
}

// 16-pt inverse DFT (e^{+i}), DIT, bit-reversed input -> natural output.
__device__ __forceinline__ void fft16_dit(float2* v)
{
    const float WR[8] = { 1.f,  0.9238795325f,  0.7071067812f,  0.3826834324f,
                          0.f, -0.3826834324f, -0.7071067812f, -0.9238795325f };
    const float WI[8] = { 0.f,  0.3826834324f,  0.7071067812f,  0.9238795325f,
                          1.f,  0.9238795325f,  0.7071067812f,  0.3826834324f };
    #pragma unroll
    for (int i = 0; i < 16; i += 2) {
        float2 a = v[i], b = v[i + 1];
        v[i]     = make_float2(a.x + b.x, a.y + b.y);
        v[i + 1] = make_float2(a.x - b.x, a.y - b.y);
    }
    #pragma unroll
    for (int i = 0; i < 16; i += 4) {
        float2 a = v[i], b = v[i + 2];
        v[i]     = make_float2(a.x + b.x, a.y + b.y);
        v[i + 2] = make_float2(a.x - b.x, a.y - b.y);
        a = v[i + 1]; b = v[i + 3];
        const float sr = -b.y, si = b.x;          // i*b
        v[i + 1] = make_float2(a.x + sr, a.y + si);
        v[i + 3] = make_float2(a.x - sr, a.y - si);
    }
    #pragma unroll
    for (int i = 0; i < 16; i += 8)
        #pragma unroll
        for (int jj = 0; jj < 4; jj++) {
            float2 a = v[i + jj], b = v[i + jj + 4];
            const float sr = b.x * WR[2 * jj] - b.y * WI[2 * jj];
            const float si = b.x * WI[2 * jj] + b.y * WR[2 * jj];
            v[i + jj]     = make_float2(a.x + sr, a.y + si);
            v[i + jj + 4] = make_float2(a.x - sr, a.y - si);
        }
    #pragma unroll
    for (int jj = 0; jj < 8; jj++) {
        float2 a = v[jj], b = v[jj + 8];
        const float sr = b.x * WR[jj] - b.y * WI[jj];
        const float si = b.x * WI[jj] + b.y * WR[jj];
        v[jj]     = make_float2(a.x + sr, a.y + si);
        v[jj + 8] = make_float2(a.x - sr, a.y - si);
    }
}

__global__ __launch_bounds__(THREADS, 4)
void istft_fused16g_kernel(const float2* __restrict__ X,
                           float* __restrict__ out)
{
    extern __shared__ char smem[];
    float2* D    = (float2*)(smem + OFF_DATA);
    float*  Frf  = (float*)(smem + OFF_DATA);
    float2* T5   = (float2*)(smem + OFF_T5);
    float2* Ttw  = (float2*)(smem + OFF_TTW);
    float2* wshp = (float2*)(smem + OFF_WSHP);
    float*  wsq  = (float*)(smem + OFF_WSQ);
    float*  einv = (float*)(smem + OFF_EINV);

    const int tid   = threadIdx.x;
    const int b     = blockIdx.x;
    const int bc    = blockIdx.y;
    const int tbase = FADV * b - 1;
    const int o0    = 256 + CHUNK * b;

    const int REV4[16] = {0,8,4,12,2,10,6,14,1,9,5,13,3,11,7,15};

    // ---- stage input first (get DRAM loads in flight) ----
    for (int idx = tid; idx < FPB * NH; idx += THREADS) {
        const int k  = idx >> 4;
        const int fr = idx & 15;
        int t = tbase + fr;
        t = t < 0 ? 0 : (t > TFRAMES - 1 ? TFRAMES - 1 : t);
        D[fr * FRSTRIDE + k] = X[(size_t)(bc * NH + k) * TFRAMES + t];
    }

    // ---- copy precomputed tables (8.8 KB, L2-resident) ----
    {
        const float4* src = (const float4*)&g_tab;
        float4* dst = (float4*)(smem + OFF_T5);
        #pragma unroll
        for (int i = tid; i < TAB_VEC4; i += THREADS)
            dst[i] = src[i];
    }
    __syncthreads();                              // barrier 1

    const int fr  = tid >> 4;
    const int col = tid & 15;                     // n1 for phase A, k2 for phase B
    float2* row = D + fr * FRSTRIDE;
    float2 v[16];

    // ---- phase A: pack onesided->complex, fft16 over n2 (DIF, bitrev out) ----
    #pragma unroll
    for (int n2 = 0; n2 < 16; n2++) {
        const int n = col + 16 * n2;
        float2 a = row[n];
        float2 t = row[256 - n];
        float br = t.x, bi = -t.y;
        if (n == 0) { a.y = 0.0f; bi = 0.0f; }    // C2R ignores DC/Nyquist imag
        const float zer = 0.5f * (a.x + br);
        const float zei = 0.5f * (a.y + bi);
        const float dr  = a.x - br;
        const float di  = a.y - bi;
        const float u   = -0.5f * di;
        const float w_  =  0.5f * dr;
        const float2 w  = T5[n];
        v[n2] = make_float2(zer + w.x * u - w.y * w_,
                            zei + w.x * w_ + w.y * u);
    }
    fft16_dif(v);                                 // v[j] = G[n1][REV4[j]]

    // ---- in-place twiddle W256^{n1*k2} via padded table ----
    #pragma unroll
    for (int j = 0; j < 16; j++)
        v[j] = cmul(v[j], Ttw[col * 17 + REV4[j]]);

    // ---- shfl transpose with REV4-mapped reg bits ----
    {
        const int MM[4] = {1, 2, 4, 8};
        const int MR[4] = {8, 4, 2, 1};
        #pragma unroll
        for (int r = 0; r < 4; r++) {
            const int m = MM[r], mr = MR[r];
            const bool sel = (col & m) != 0;
            #pragma unroll
            for (int j0 = 0; j0 < 16; j0++) {
                if (j0 & mr) continue;
                const int j1 = j0 | mr;
                float2 tmp = sel ? v[j0] : v[j1];
                tmp.x = __shfl_xor_sync(0xFFFFFFFFu, tmp.x, m, 16);
                tmp.y = __shfl_xor_sync(0xFFFFFFFFu, tmp.y, m, 16);
                if (sel) v[j0] = tmp; else v[j1] = tmp;
            }
        }
    }
    // lane k2, reg j holds H[REV4[j]][k2] -> bitrev input for DIT

    // ---- phase B: fft16 over n1 (DIT, natural out); windowed frame write ----
    fft16_dit(v);
    #pragma unroll
    for (int k1 = 0; k1 < 16; k1++) {
        const int m = col + 16 * k1;              // col = k2 here
        const float2 z  = v[k1];
        const float2 wp = wshp[m];
        row[m] = make_float2(z.x * wp.x, z.y * wp.y);
    }
    __syncthreads();                              // barrier 2

    // ---- overlap-add + envelope normalize (vectorized x4) ----
    const int ngroups = min(CHUNK, 262272 - o0) >> 2;
    const size_t obase = (size_t)bc * OUT_PER_BC;
    for (int g = tid; g < ngroups; g += THREADS) {
        const int m0 = o0 + 4 * g;
        if (m0 >= 384 && m0 + 3 < 262144) {
            const int t0   = (m0 - 384) >> 7;
            const int n0   = m0 - (t0 << 7);                  // 384..508, %4==0
            const int base = (t0 - tbase) * (2 * FRSTRIDE) + n0;
            const float4 a = *(const float4*)(Frf + base);
            const float4 bb = *(const float4*)(Frf + base + 400);
            const float4 c = *(const float4*)(Frf + base + 800);
            const float4 d = *(const float4*)(Frf + base + 1200);
            const float4 e = *(const float4*)(einv + (n0 & 127));
            float4 r;
            r.x = (a.x + bb.x + c.x + d.x) * e.x;
            r.y = (a.y + bb.y + c.y + d.y) * e.y;
            r.z = (a.z + bb.z + c.z + d.z) * e.z;
            r.w = (a.w + bb.w + c.w + d.w) * e.w;
            *(float4*)(out + obase + (m0 - 256)) = r;
        } else {
            #pragma unroll
            for (int q = 0; q < 4; q++) {
                const int m = m0 + q;
                int thi = m >> 7;          if (thi > TFRAMES - 1) thi = TFRAMES - 1;
                int tlo = (m - 384) >> 7;  if (tlo < 0) tlo = 0;
                float acc = 0.0f, e = 0.0f;
                for (int t_ = tlo; t_ <= thi; t_++) {
                    const int n = m - (t_ << 7);
                    acc += Frf[(t_ - tbase) * (2 * FRSTRIDE) + n];
                    e   += wsq[n];
                }
                out[obase + (m - 256)] = acc / e;
            }
        }
    }
}

extern "C" void kernel_launch(void* const* d_in, const int* in_sizes, int n_in,
                              void* d_out, int out_size)
{
    const float2* X   = (const float2*)d_in[0];   // (16,2,257,2048,2) f32
    const float*  win = (const float*)d_in[1];    // (512,) f32
    float* out = (float*)d_out;                   // (16,2,262016) f32

    istft_init_tables<<<1, THREADS>>>(win);       // same stream -> ordered

    dim3 grid(NCHUNK, NBC);
    istft_fused16g_kernel<<<grid, THREADS, SMEM_BYTES>>>(X, out);
}